// round 12
// baseline (speedup 1.0000x reference)
#include <cuda_runtime.h>
#include <cuda_bf16.h>
#include <cstdint>

#define TLEN 1024
#define BSZ  128
#define DIN  64
#define HD   512
#define N0CTA 64
#define N1CTA 64
#define NALL  128
#define NTHR  256

// fragment index: uint4 element for (16-row block R, 16-k block C, lane l)
#define FIDX(R, C, l) ((((R) * 32 + (C)) * 32) + (l))

// ---------------- device scratch (static, no allocations) ----------------
__device__ float g_xg[268435456];          // 1 GB: L0 xg frags [t][cta][mf][nf][l][4]
__device__ uint4 g_h0f[8][8192];           // h0 bf16 A-frag ring (8 deep)
__device__ uint4 g_h1f[2][8192];           // h1 double buffer
__device__ uint4 g_zf[8192];               // stays zero
// hierarchical barrier state: 8 sub-counters per group (one per 256B line) + master
__device__ __align__(256) unsigned g_sub0[8 * 64];
__device__ __align__(256) unsigned g_mst0[64];
__device__ __align__(256) unsigned g_sub1[8 * 64];
__device__ __align__(256) unsigned g_mst1[64];
__device__ __align__(256) unsigned g_finp[64];

// ---------------- helpers ----------------
__device__ __forceinline__ uint32_t tf32u(float x) {
    uint32_t u; asm("cvt.rna.tf32.f32 %0, %1;" : "=r"(u) : "f"(x)); return u;
}
__device__ __forceinline__ float tf32r(float x) { return __uint_as_float(tf32u(x)); }

__device__ __forceinline__ void mma8(float d[4], const uint32_t a[4], uint32_t b0, uint32_t b1) {
    asm volatile("mma.sync.aligned.m16n8k8.row.col.f32.tf32.tf32.f32 "
        "{%0,%1,%2,%3}, {%4,%5,%6,%7}, {%8,%9}, {%0,%1,%2,%3};"
        : "+f"(d[0]), "+f"(d[1]), "+f"(d[2]), "+f"(d[3])
        : "r"(a[0]), "r"(a[1]), "r"(a[2]), "r"(a[3]), "r"(b0), "r"(b1));
}
__device__ __forceinline__ void mma16(float d[4], const uint32_t* a, uint32_t b0, uint32_t b1) {
    asm volatile("mma.sync.aligned.m16n8k16.row.col.f32.bf16.bf16.f32 "
        "{%0,%1,%2,%3}, {%4,%5,%6,%7}, {%8,%9}, {%0,%1,%2,%3};"
        : "+f"(d[0]), "+f"(d[1]), "+f"(d[2]), "+f"(d[3])
        : "r"(a[0]), "r"(a[1]), "r"(a[2]), "r"(a[3]), "r"(b0), "r"(b1));
}

__device__ __forceinline__ float sigm(float x)  { return 1.0f / (1.0f + __expf(-x)); }
__device__ __forceinline__ float tanhp(float x) { return 2.0f / (1.0f + __expf(-2.0f * x)) - 1.0f; }

// hierarchical arrive: acq_rel add on own sub-line; 8th arriver releases +8 to master
__device__ __forceinline__ void arrive_hier(unsigned* sub, unsigned* mst, int idx) {
    unsigned old;
    asm volatile("atom.add.acq_rel.gpu.global.u32 %0, [%1], 1;"
                 : "=r"(old) : "l"(sub + (idx & 7) * 64) : "memory");
    if (((old + 1) & 7) == 0)
        asm volatile("red.release.gpu.global.add.u32 [%0], 8;" :: "l"(mst) : "memory");
}
__device__ __forceinline__ void poll_ge(unsigned* c, unsigned tgt) {
    unsigned v;
    do {
        asm volatile("ld.acquire.gpu.global.u32 %0, [%1];" : "=r"(v) : "l"(c) : "memory");
    } while (v < tgt);
}
// block-wide: arrive own group and wait for whole group (master = 64/epoch)
__device__ __forceinline__ void group_barrier(unsigned* sub, unsigned* mst, int idx, unsigned tgt64) {
    __syncthreads();
    if (threadIdx.x == 0) { arrive_hier(sub, mst, idx); poll_ge(mst, tgt64); }
    __syncthreads();
}
// warp-scope wait on other group's master
__device__ __forceinline__ void warp_wait(unsigned* mst, unsigned tgt64) {
    if ((threadIdx.x & 31) == 0) poll_ge(mst, tgt64);
    __syncwarp();
}

// LSTM epilogue on one row-block (R), 4 nf frags
__device__ __forceinline__ void epi4(float D[4][4], float* cst, char* hbuf,
                                     int ubase, int R, int l) {
    const int gr = l >> 2, tq = l & 3;
    const bool odd = tq & 1;
    #pragma unroll
    for (int nf = 0; nf < 4; ++nf) {
        float d0 = D[nf][0], d1 = D[nf][1], d2 = D[nf][2], d3 = D[nf][3];
        float p0 = __shfl_xor_sync(0xffffffffu, d0, 1);
        float p1 = __shfl_xor_sync(0xffffffffu, d1, 1);
        float p2 = __shfl_xor_sync(0xffffffffu, d2, 1);
        float p3 = __shfl_xor_sync(0xffffffffu, d3, 1);
        float gi = odd ? p2 : d0;
        float gf = odd ? p3 : d1;
        float gg = odd ? d2 : p0;
        float go = odd ? d3 : p1;
        float c = sigm(gf) * cst[nf] + sigm(gi) * tanhp(gg);
        cst[nf] = c;
        float h = sigm(go) * tanhp(c);
        float hp = __shfl_xor_sync(0xffffffffu, h, 2);
        if (!(tq & 2)) {                       // owns even unit; partner has u+1
            int u = ubase + nf * 2;
            int nfc = (u & 15) >> 1;
            __nv_bfloat162 pk(__float2bfloat16(h), __float2bfloat16(hp));
            size_t off = (size_t)(((R * 32 + (u >> 4)) * 32) + gr * 4 + (nfc & 3)) * 16
                       + ((odd ? 1 : 0) + 2 * (nfc >> 2)) * 4;
            *(uint32_t*)(hbuf + off) = *(uint32_t*)&pk;
        }
    }
}

// =====================================================================
// xform0: g_xg = bias + x @ Wih0^T in per-thread D-fragment layout.
// =====================================================================
#define XW_ST 36
__global__ void __launch_bounds__(NTHR, 1)
xform0(const float* __restrict__ x, const float* __restrict__ Wih,
       const float* __restrict__ bih, const float* __restrict__ bhh)
{
    extern __shared__ float sm[];
    float* Ws = sm;                  // [64][XW_ST]
    float* bs = sm + 64 * XW_ST;

    const int tid = threadIdx.x, l = tid & 31, w = tid >> 5;
    const int gr = l >> 2, tq = l & 3;
    const int cta = blockIdx.x;

    for (int i = tid; i < 64 * 32; i += NTHR) {
        int k = i >> 5, c = i & 31;
        int gate = c & 3, ul = c >> 2;
        int grow = gate * HD + cta * 8 + ul;
        Ws[k * XW_ST + c] = tf32r(Wih[(size_t)grow * DIN + k]);
    }
    if (tid < 32) {
        int gate = tid & 3, ul = tid >> 2;
        int grow = gate * HD + cta * 8 + ul;
        bs[tid] = bih[grow] + bhh[grow];
    }
    __syncthreads();

    const int r0 = 16 * w + gr;
    for (int tt = 0; tt < 8; ++tt) {
        const int t = blockIdx.y * 8 + tt;
        float D[4][4];
        #pragma unroll
        for (int nf = 0; nf < 4; ++nf) {
            float b0 = bs[nf * 8 + 2 * tq];
            float b1 = bs[nf * 8 + 2 * tq + 1];
            D[nf][0] = b0; D[nf][1] = b1; D[nf][2] = b0; D[nf][3] = b1;
        }
        #pragma unroll
        for (int kk = 0; kk < 8; ++kk) {
            const int ko = kk * 8;
            const float* xp  = x + (size_t)r0 * (TLEN * DIN) + (size_t)t * DIN + ko + tq;
            const float* xp8 = xp + (size_t)8 * (TLEN * DIN);
            uint32_t a[4] = { tf32u(xp[0]), tf32u(xp8[0]), tf32u(xp[4]), tf32u(xp8[4]) };
            #pragma unroll
            for (int nf = 0; nf < 4; ++nf) {
                uint32_t b0 = __float_as_uint(Ws[(ko + tq) * XW_ST + nf * 8 + gr]);
                uint32_t b1 = __float_as_uint(Ws[(ko + tq + 4) * XW_ST + nf * 8 + gr]);
                mma8(D[nf], a, b0, b1);
            }
        }
        float* dst = g_xg + ((((size_t)t * N0CTA + cta) * 8 + w) * 4) * 128 + l * 4;
        #pragma unroll
        for (int nf = 0; nf < 4; ++nf)
            *(float4*)(dst + nf * 128) = make_float4(D[nf][0], D[nf][1], D[nf][2], D[nf][3]);
    }
}

// =====================================================================
// rec: 128 persistent CTAs, two decoupled groups, K-split warp pairs,
// hierarchical barriers, distance-2 A prefetch (mod-3 register ring).
// =====================================================================
#define OFF_BIAS 65536
#define OFF_XCH  66048
#define SMEM_REC (OFF_XCH + 16384)

__global__ void __launch_bounds__(NTHR, 1)
rec(const float* __restrict__ Whh0,
    const float* __restrict__ Wih1, const float* __restrict__ Whh1,
    const float* __restrict__ bih1, const float* __restrict__ bhh1,
    const float* __restrict__ fc1w, const float* __restrict__ fc1b,
    const float* __restrict__ fc2w, const float* __restrict__ fc2b,
    float* __restrict__ out)
{
    extern __shared__ char smc[];
    uint4* Wf  = (uint4*)smc;
    float* bsm = (float*)(smc + OFF_BIAS);
    float4* xch = (float4*)(smc + OFF_XCH);    // [w][j 0..3][lane]

    const int tid = threadIdx.x, l = tid & 31, w = tid >> 5;
    const int tq = l & 3;
    const int wq = w & 3, kh = w >> 2;
    const int mfA = 2 * wq, mfB = 2 * wq + 1;
    const int fin = 2 * wq + kh;               // row-block this warp finalizes
    const int cta = blockIdx.x;
    const bool is0 = (cta < N0CTA);
    const int lc = is0 ? cta : (cta - N0CTA);

    // ---- stage weights into B-fragment smem layout (once) ----
    {
        const int nkp = is0 ? 256 : 512;    // k-pairs
        for (int i = tid; i < nkp * 32; i += NTHR) {
            int c = i & 31, kp = i >> 5, k = kp * 2;
            int gate = c & 3, ul = c >> 2;
            int grow = gate * HD + lc * 8 + ul;
            float w0, w1;
            if (is0)        { w0 = Whh0[(size_t)grow * HD + k];      w1 = Whh0[(size_t)grow * HD + k + 1]; }
            else if (k < HD){ w0 = Wih1[(size_t)grow * HD + k];      w1 = Wih1[(size_t)grow * HD + k + 1]; }
            else            { w0 = Whh1[(size_t)grow * HD + k - HD]; w1 = Whh1[(size_t)grow * HD + k - HD + 1]; }
            int C = k >> 4, C2 = C >> 1, Codd = C & 1;
            size_t off = ((size_t)(C2 * 4 + (c >> 3)) * 32 + 4 * (c & 7) + (kp & 3)) * 16
                       + (Codd * 2 + ((kp >> 2) & 1)) * 4;
            *(__nv_bfloat162*)(smc + off) =
                __nv_bfloat162(__float2bfloat16(w0), __float2bfloat16(w1));
        }
        if (!is0 && tid < 32) {
            int gate = tid & 3, ul = tid >> 2;
            int grow = gate * HD + lc * 8 + ul;
            bsm[tid] = bih1[grow] + bhh1[grow];
        }
    }
    __syncthreads();

    float cst[4] = {0.0f, 0.0f, 0.0f, 0.0f};

    if (is0) {
        // ================= layer 0 group =================
        for (int e = 0; e < TLEN; ++e) {
            const float* xp = g_xg + ((((size_t)e * N0CTA + cta) * 8 + fin) * 4) * 128 + l * 4;
            float4 xv[4];
            #pragma unroll
            for (int f = 0; f < 4; ++f) xv[f] = __ldcs((const float4*)(xp + f * 128));

            const uint4* Ab = e ? g_h0f[(e - 1) & 7] : g_zf;
            float P[2][4][4];
            #pragma unroll
            for (int m = 0; m < 2; ++m)
                #pragma unroll
                for (int nf = 0; nf < 4; ++nf)
                    #pragma unroll
                    for (int q = 0; q < 4; ++q) P[m][nf][q] = 0.0f;

            // mod-3 ring, distance-2 prefetch over 8 iterations
            uint4 aa[3][4];
            #pragma unroll
            for (int p = 0; p < 2; ++p) {
                const int C = kh * 16 + 2 * p;
                aa[p][0] = __ldcg(&Ab[FIDX(mfA, C,     l)]);
                aa[p][1] = __ldcg(&Ab[FIDX(mfA, C + 1, l)]);
                aa[p][2] = __ldcg(&Ab[FIDX(mfB, C,     l)]);
                aa[p][3] = __ldcg(&Ab[FIDX(mfB, C + 1, l)]);
            }
            #pragma unroll
            for (int i = 0; i < 8; ++i) {
                const int cur = i % 3;
                if (i + 2 < 8) {
                    const int nxt = (i + 2) % 3;
                    const int C = kh * 16 + 2 * (i + 2);
                    aa[nxt][0] = __ldcg(&Ab[FIDX(mfA, C,     l)]);
                    aa[nxt][1] = __ldcg(&Ab[FIDX(mfA, C + 1, l)]);
                    aa[nxt][2] = __ldcg(&Ab[FIDX(mfB, C,     l)]);
                    aa[nxt][3] = __ldcg(&Ab[FIDX(mfB, C + 1, l)]);
                }
                const int C2 = kh * 8 + i;
                #pragma unroll
                for (int nf = 0; nf < 4; ++nf) {
                    uint4 bq = Wf[(C2 * 4 + nf) * 32 + l];
                    mma16(P[0][nf], (const uint32_t*)&aa[cur][0], bq.x, bq.y);
                    mma16(P[0][nf], (const uint32_t*)&aa[cur][1], bq.z, bq.w);
                    mma16(P[1][nf], (const uint32_t*)&aa[cur][2], bq.x, bq.y);
                    mma16(P[1][nf], (const uint32_t*)&aa[cur][3], bq.z, bq.w);
                }
            }

            // exchange: store partner's row-block partial (index 1-kh)
            #pragma unroll
            for (int nf = 0; nf < 4; ++nf)
                xch[(w * 4 + nf) * 32 + l] = make_float4(P[1 - kh][nf][0], P[1 - kh][nf][1],
                                                          P[1 - kh][nf][2], P[1 - kh][nf][3]);
            // ring back-pressure folded into the reduction sync
            if (tid == 0 && e >= 8) poll_ge(g_mst1, 64u * (unsigned)(e - 7));
            __syncthreads();

            float D[4][4];
            #pragma unroll
            for (int nf = 0; nf < 4; ++nf) {
                float4 q = xch[((w ^ 4) * 4 + nf) * 32 + l];
                D[nf][0] = P[kh][nf][0] + q.x + (&xv[nf].x)[0];
                D[nf][1] = P[kh][nf][1] + q.y + (&xv[nf].x)[1];
                D[nf][2] = P[kh][nf][2] + q.z + (&xv[nf].x)[2];
                D[nf][3] = P[kh][nf][3] + q.w + (&xv[nf].x)[3];
            }
            epi4(D, cst, (char*)g_h0f[e & 7], cta * 8, fin, l);
            group_barrier(g_sub0, g_mst0, cta, 64u * (unsigned)(e + 1));
        }
    } else {
        // ================= layer 1 group (trails L0) =================
        for (int e = 1; e <= TLEN; ++e) {
            const uint4* Ab;
            int C2base;
            if (kh == 1) {                       // own h1 half — no external wait
                Ab = (e >= 2) ? g_h1f[e & 1] : g_zf;
                C2base = 16;
            } else {                             // h0 half — warp-scope wait
                warp_wait(g_mst0, 64u * (unsigned)e);
                Ab = g_h0f[(e - 1) & 7];
                C2base = 0;
            }

            float P[2][4][4];
            #pragma unroll
            for (int m = 0; m < 2; ++m)
                #pragma unroll
                for (int nf = 0; nf < 4; ++nf)
                    #pragma unroll
                    for (int q = 0; q < 4; ++q) P[m][nf][q] = 0.0f;

            uint4 aa[3][4];
            #pragma unroll
            for (int p = 0; p < 2; ++p) {
                const int C = 2 * p;
                aa[p][0] = __ldcg(&Ab[FIDX(mfA, C,     l)]);
                aa[p][1] = __ldcg(&Ab[FIDX(mfA, C + 1, l)]);
                aa[p][2] = __ldcg(&Ab[FIDX(mfB, C,     l)]);
                aa[p][3] = __ldcg(&Ab[FIDX(mfB, C + 1, l)]);
            }
            #pragma unroll
            for (int i = 0; i < 16; ++i) {
                const int cur = i % 3;
                if (i + 2 < 16) {
                    const int nxt = (i + 2) % 3;
                    const int C = 2 * (i + 2);
                    aa[nxt][0] = __ldcg(&Ab[FIDX(mfA, C,     l)]);
                    aa[nxt][1] = __ldcg(&Ab[FIDX(mfA, C + 1, l)]);
                    aa[nxt][2] = __ldcg(&Ab[FIDX(mfB, C,     l)]);
                    aa[nxt][3] = __ldcg(&Ab[FIDX(mfB, C + 1, l)]);
                }
                const int C2 = C2base + i;
                #pragma unroll
                for (int nf = 0; nf < 4; ++nf) {
                    uint4 bq = Wf[(C2 * 4 + nf) * 32 + l];
                    mma16(P[0][nf], (const uint32_t*)&aa[cur][0], bq.x, bq.y);
                    mma16(P[0][nf], (const uint32_t*)&aa[cur][1], bq.z, bq.w);
                    mma16(P[1][nf], (const uint32_t*)&aa[cur][2], bq.x, bq.y);
                    mma16(P[1][nf], (const uint32_t*)&aa[cur][3], bq.z, bq.w);
                }
            }

            #pragma unroll
            for (int nf = 0; nf < 4; ++nf)
                xch[(w * 4 + nf) * 32 + l] = make_float4(P[1 - kh][nf][0], P[1 - kh][nf][1],
                                                          P[1 - kh][nf][2], P[1 - kh][nf][3]);
            __syncthreads();

            float D[4][4];
            #pragma unroll
            for (int nf = 0; nf < 4; ++nf) {
                float4 q = xch[((w ^ 4) * 4 + nf) * 32 + l];
                float b0 = bsm[nf * 8 + 2 * tq];
                float b1 = bsm[nf * 8 + 2 * tq + 1];
                D[nf][0] = P[kh][nf][0] + q.x + b0;
                D[nf][1] = P[kh][nf][1] + q.y + b1;
                D[nf][2] = P[kh][nf][2] + q.z + b0;
                D[nf][3] = P[kh][nf][3] + q.w + b1;
            }
            epi4(D, cst, (char*)g_h1f[(e - 1) & 1], lc * 8, fin, l);
            group_barrier(g_sub1, g_mst1, lc, 64u * (unsigned)e);
        }
    }

    // ---------------- FC head on CTA 0 ----------------
    if (cta == 0) {
        if (tid == 0) poll_ge(g_mst1, 64u * (unsigned)TLEN);
        __syncthreads();
        float* sw = (float*)smc;                     // reuse weight region
        for (int i = tid; i < HD * 32; i += NTHR) {
            int u = i >> 5, j = i & 31;
            sw[i] = fc1w[(size_t)j * HD + u];
        }
        __syncthreads();
        if (tid < BSZ) {
            const uint4* hb = g_h1f[(TLEN - 1) & 1];
            float s[32];
            #pragma unroll
            for (int j = 0; j < 32; ++j) s[j] = 0.0f;
            for (int u = 0; u < HD; ++u) {
                uint4 q = __ldcg(&hb[FIDX(tid >> 4, u >> 4, (tid & 7) * 4 + ((u & 7) >> 1))]);
                uint32_t rg = ((const uint32_t*)&q)[((tid >> 3) & 1) + 2 * ((u >> 3) & 1)];
                float v = __bfloat162float(((const __nv_bfloat16*)&rg)[u & 1]);
                const float4* ww = (const float4*)(sw + u * 32);
                #pragma unroll
                for (int j4 = 0; j4 < 8; ++j4) {
                    float4 wv = ww[j4];
                    s[4 * j4 + 0] += v * wv.x;
                    s[4 * j4 + 1] += v * wv.y;
                    s[4 * j4 + 2] += v * wv.z;
                    s[4 * j4 + 3] += v * wv.w;
                }
            }
            float y = fc2b[0];
            #pragma unroll
            for (int j = 0; j < 32; ++j) y += fc2w[j] * (s[j] + fc1b[j]);
            out[tid] = y;
        }
        __syncthreads();
    }

    // ---------------- finalize: reset counters for graph replay ----------------
    __syncthreads();
    __threadfence();
    if (tid == 0) {
        if (atomicAdd(&g_finp[0], 1u) == NALL - 1) {
            #pragma unroll
            for (int s = 0; s < 8; ++s) { g_sub0[s * 64] = 0; g_sub1[s * 64] = 0; }
            g_mst0[0] = 0;
            g_mst1[0] = 0;
            __threadfence();
            atomicExch(&g_finp[0], 0u);
        }
    }
}

// =====================================================================
extern "C" void kernel_launch(void* const* d_in, const int* in_sizes, int n_in,
                              void* d_out, int out_size)
{
    (void)in_sizes; (void)n_in; (void)out_size;
    const float* x    = (const float*)d_in[0];
    const float* Wih0 = (const float*)d_in[1];
    const float* Whh0 = (const float*)d_in[2];
    const float* bih0 = (const float*)d_in[3];
    const float* bhh0 = (const float*)d_in[4];
    const float* Wih1 = (const float*)d_in[5];
    const float* Whh1 = (const float*)d_in[6];
    const float* bih1 = (const float*)d_in[7];
    const float* bhh1 = (const float*)d_in[8];
    const float* fc1w = (const float*)d_in[9];
    const float* fc1b = (const float*)d_in[10];
    const float* fc2w = (const float*)d_in[11];
    const float* fc2b = (const float*)d_in[12];
    float* out = (float*)d_out;

    const int sm_x = 64 * XW_ST * 4 + 256;
    cudaFuncSetAttribute(xform0, cudaFuncAttributeMaxDynamicSharedMemorySize, sm_x);
    cudaFuncSetAttribute(rec,    cudaFuncAttributeMaxDynamicSharedMemorySize, SMEM_REC);

    xform0<<<dim3(N0CTA, TLEN / 8), NTHR, sm_x>>>(x, Wih0, bih0, bhh0);
    rec<<<NALL, NTHR, SMEM_REC>>>(Whh0, Wih1, Whh1, bih1, bhh1,
                                  fc1w, fc1b, fc2w, fc2b, out);
}

// round 13
// speedup vs baseline: 1.2237x; 1.2237x over previous
#include <cuda_runtime.h>
#include <cuda_bf16.h>
#include <cstdint>

#define TLEN 1024
#define BSZ  128
#define DIN  64
#define HD   512
#define N0CTA 64
#define N1CTA 64
#define NALL  128
#define NTHR  256

// fragment index: uint4 element for (16-row block R, 16-k block C(0..31), lane l)
#define FIDX(R, C, l) ((((R) * 32 + (C)) * 32) + (l))

// ---------------- device scratch (static, no allocations) ----------------
__device__ uint4 g_xf[(size_t)TLEN * 1024];   // 16 MB: x bf16 A-frags [t][R][C0..3][l]
__device__ uint4 g_h0f[8][8192];              // h0 bf16 A-frag ring (8 deep)
__device__ uint4 g_h1f[2][8192];              // h1 double buffer
__device__ uint4 g_zf[8192];                  // stays zero
// barrier state: 8 sub-counter lines per group (each on its own 256B line)
__device__ __align__(256) unsigned g_sub0[8 * 64];
__device__ __align__(256) unsigned g_sub1[8 * 64];
__device__ __align__(256) unsigned g_finp[64];

// ---------------- helpers ----------------
__device__ __forceinline__ void mma16(float d[4], const uint32_t* a, uint32_t b0, uint32_t b1) {
    asm volatile("mma.sync.aligned.m16n8k16.row.col.f32.bf16.bf16.f32 "
        "{%0,%1,%2,%3}, {%4,%5,%6,%7}, {%8,%9}, {%0,%1,%2,%3};"
        : "+f"(d[0]), "+f"(d[1]), "+f"(d[2]), "+f"(d[3])
        : "r"(a[0]), "r"(a[1]), "r"(a[2]), "r"(a[3]), "r"(b0), "r"(b1));
}

__device__ __forceinline__ float sigm(float x)  { return 1.0f / (1.0f + __expf(-x)); }
__device__ __forceinline__ float tanhp(float x) { return 2.0f / (1.0f + __expf(-2.0f * x)) - 1.0f; }

__device__ __forceinline__ void red_rel(unsigned* c) {
    asm volatile("red.release.gpu.global.add.u32 [%0], 1;" :: "l"(c) : "memory");
}
__device__ __forceinline__ unsigned ld_acq(const unsigned* c) {
    unsigned v;
    asm volatile("ld.acquire.gpu.global.u32 %0, [%1];" : "=r"(v) : "l"(c) : "memory");
    return v;
}
// full-warp poll: lanes 0..7 read the 8 sub-lines in parallel, reduce, repeat
__device__ __forceinline__ void warp_poll8(unsigned* sub, unsigned tgt) {
    const int l = threadIdx.x & 31;
    unsigned s;
    do {
        unsigned v = (l < 8) ? ld_acq(sub + l * 64) : 0u;
        s = __reduce_add_sync(0xffffffffu, v);
    } while (s < tgt);
}
// block-wide: arrive on own sub-line, warp 0 polls the 8 lines
__device__ __forceinline__ void group_barrier8(unsigned* sub, int idx, unsigned tgt) {
    __syncthreads();
    if (threadIdx.x < 32) {
        if (threadIdx.x == 0) red_rel(sub + (idx & 7) * 64);
        warp_poll8(sub, tgt);
    }
    __syncthreads();
}

// LSTM epilogue on one row-block (R), 4 nf frags (unchanged from R11)
__device__ __forceinline__ void epi4(float D[4][4], float* cst, char* hbuf,
                                     int ubase, int R, int l) {
    const int gr = l >> 2, tq = l & 3;
    const bool odd = tq & 1;
    #pragma unroll
    for (int nf = 0; nf < 4; ++nf) {
        float d0 = D[nf][0], d1 = D[nf][1], d2 = D[nf][2], d3 = D[nf][3];
        float p0 = __shfl_xor_sync(0xffffffffu, d0, 1);
        float p1 = __shfl_xor_sync(0xffffffffu, d1, 1);
        float p2 = __shfl_xor_sync(0xffffffffu, d2, 1);
        float p3 = __shfl_xor_sync(0xffffffffu, d3, 1);
        float gi = odd ? p2 : d0;
        float gf = odd ? p3 : d1;
        float gg = odd ? d2 : p0;
        float go = odd ? d3 : p1;
        float c = sigm(gf) * cst[nf] + sigm(gi) * tanhp(gg);
        cst[nf] = c;
        float h = sigm(go) * tanhp(c);
        float hp = __shfl_xor_sync(0xffffffffu, h, 2);
        if (!(tq & 2)) {                       // owns even unit; partner has u+1
            int u = ubase + nf * 2;
            int nfc = (u & 15) >> 1;
            __nv_bfloat162 pk(__float2bfloat16(h), __float2bfloat16(hp));
            size_t off = (size_t)(((R * 32 + (u >> 4)) * 32) + gr * 4 + (nfc & 3)) * 16
                       + ((odd ? 1 : 0) + 2 * (nfc >> 2)) * 4;
            *(uint32_t*)(hbuf + off) = *(uint32_t*)&pk;
        }
    }
}

// =====================================================================
// xprep: convert x[b][t][d] (f32) into per-t bf16 A-fragment tiles.
// grid = TLEN blocks, 256 threads; each thread writes 4 uint4.
// =====================================================================
__global__ void __launch_bounds__(256, 1)
xprep(const float* __restrict__ x)
{
    const int t = blockIdx.x;
    const int tid = threadIdx.x;
    #pragma unroll
    for (int j = 0; j < 4; ++j) {
        int id = tid + j * 256;
        int R = id >> 7, C = (id >> 5) & 3, l = id & 31;
        int gr = l >> 2, tq = l & 3;
        int r0 = 16 * R + gr;
        int k0 = 16 * C + 2 * tq;
        const float* p0 = x + (size_t)r0 * (TLEN * DIN) + (size_t)t * DIN;
        const float* p1 = p0 + (size_t)8 * (TLEN * DIN);
        __nv_bfloat162 X(__float2bfloat16(p0[k0]),     __float2bfloat16(p0[k0 + 1]));
        __nv_bfloat162 Y(__float2bfloat16(p1[k0]),     __float2bfloat16(p1[k0 + 1]));
        __nv_bfloat162 Z(__float2bfloat16(p0[k0 + 8]), __float2bfloat16(p0[k0 + 9]));
        __nv_bfloat162 W(__float2bfloat16(p1[k0 + 8]), __float2bfloat16(p1[k0 + 9]));
        uint4 v;
        v.x = *(uint32_t*)&X; v.y = *(uint32_t*)&Y;
        v.z = *(uint32_t*)&Z; v.w = *(uint32_t*)&W;
        g_xf[(size_t)t * 1024 + id] = v;
    }
}

// =====================================================================
// rec: 128 persistent CTAs, two decoupled groups, K-split warp pairs.
//   CTA 0..63   : layer0, K=576 = [x(t) 64 ; h0(t-1) 512], 18 C2-chunks (9/kh)
//   CTA 64..127 : layer1, K=1024 = [h0(t) ; h1(t-1)], 32 C2-chunks (16/kh)
// Barrier: 8-line flat counters, fire-and-forget RED, full-warp 8-line poll.
// =====================================================================
#define OFF_BIAS 65536
#define OFF_XCH  66048
#define SMEM_REC (OFF_XCH + 16384)

__global__ void __launch_bounds__(NTHR, 1)
rec(const float* __restrict__ Wih0, const float* __restrict__ Whh0,
    const float* __restrict__ bih0, const float* __restrict__ bhh0,
    const float* __restrict__ Wih1, const float* __restrict__ Whh1,
    const float* __restrict__ bih1, const float* __restrict__ bhh1,
    const float* __restrict__ fc1w, const float* __restrict__ fc1b,
    const float* __restrict__ fc2w, const float* __restrict__ fc2b,
    float* __restrict__ out)
{
    extern __shared__ char smc[];
    uint4* Wf  = (uint4*)smc;
    float* bsm = (float*)(smc + OFF_BIAS);
    float4* xch = (float4*)(smc + OFF_XCH);    // [w][j 0..3][lane]

    const int tid = threadIdx.x, l = tid & 31, w = tid >> 5;
    const int tq = l & 3;
    const int wq = w & 3, kh = w >> 2;
    const int mfA = 2 * wq, mfB = 2 * wq + 1;
    const int fin = 2 * wq + kh;               // row-block this warp finalizes
    const int cta = blockIdx.x;
    const bool is0 = (cta < N0CTA);
    const int lc = is0 ? cta : (cta - N0CTA);

    // ---- stage weights into B-fragment smem layout (once) ----
    {
        const int nkp = is0 ? 288 : 512;    // k-pairs (L0: K=576, L1: K=1024)
        for (int i = tid; i < nkp * 32; i += NTHR) {
            int c = i & 31, kp = i >> 5, k = kp * 2;
            int gate = c & 3, ul = c >> 2;
            int grow = gate * HD + lc * 8 + ul;
            float w0, w1;
            if (is0) {
                if (k < DIN) { w0 = Wih0[(size_t)grow * DIN + k];        w1 = Wih0[(size_t)grow * DIN + k + 1]; }
                else         { w0 = Whh0[(size_t)grow * HD + k - DIN];   w1 = Whh0[(size_t)grow * HD + k - DIN + 1]; }
            } else {
                if (k < HD)  { w0 = Wih1[(size_t)grow * HD + k];         w1 = Wih1[(size_t)grow * HD + k + 1]; }
                else         { w0 = Whh1[(size_t)grow * HD + k - HD];    w1 = Whh1[(size_t)grow * HD + k - HD + 1]; }
            }
            int C = k >> 4, C2 = C >> 1, Codd = C & 1;
            size_t off = ((size_t)(C2 * 4 + (c >> 3)) * 32 + 4 * (c & 7) + (kp & 3)) * 16
                       + (Codd * 2 + ((kp >> 2) & 1)) * 4;
            *(__nv_bfloat162*)(smc + off) =
                __nv_bfloat162(__float2bfloat16(w0), __float2bfloat16(w1));
        }
        if (tid < 32) {
            int gate = tid & 3, ul = tid >> 2;
            int grow = gate * HD + lc * 8 + ul;
            bsm[tid] = is0 ? (bih0[grow] + bhh0[grow]) : (bih1[grow] + bhh1[grow]);
        }
    }
    __syncthreads();

    float cst[4] = {0.0f, 0.0f, 0.0f, 0.0f};

    if (is0) {
        // ================= layer 0 group =================
        // per-iter global C2 index g = kh*9 + i (0..17); A C-chunks cc = 2g, 2g+1;
        // cc < 4 -> x frags, else h0 C-chunk cc-4.
        for (int e = 0; e < TLEN; ++e) {
            const uint4* xf = g_xf + (size_t)e * 1024;
            const uint4* Ab = e ? g_h0f[(e - 1) & 7] : g_zf;
            #define LDA0(R, cc) ((cc) < 4 ? __ldg(&xf[(((R) * 4 + (cc)) * 32) + l]) \
                                          : __ldcg(&Ab[FIDX((R), (cc) - 4, l)]))
            float P[2][4][4];
            #pragma unroll
            for (int m = 0; m < 2; ++m)
                #pragma unroll
                for (int nf = 0; nf < 4; ++nf)
                    #pragma unroll
                    for (int q = 0; q < 4; ++q) P[m][nf][q] = 0.0f;

            uint4 aa[2][4];
            {
                const int g0 = kh * 9;
                aa[0][0] = LDA0(mfA, 2 * g0);
                aa[0][1] = LDA0(mfA, 2 * g0 + 1);
                aa[0][2] = LDA0(mfB, 2 * g0);
                aa[0][3] = LDA0(mfB, 2 * g0 + 1);
            }
            #pragma unroll
            for (int i = 0; i < 9; ++i) {
                const int cur = i & 1, nxt = cur ^ 1;
                if (i < 8) {
                    const int g2 = kh * 9 + i + 1;
                    aa[nxt][0] = LDA0(mfA, 2 * g2);
                    aa[nxt][1] = LDA0(mfA, 2 * g2 + 1);
                    aa[nxt][2] = LDA0(mfB, 2 * g2);
                    aa[nxt][3] = LDA0(mfB, 2 * g2 + 1);
                }
                const int C2 = kh * 9 + i;
                #pragma unroll
                for (int nf = 0; nf < 4; ++nf) {
                    uint4 bq = Wf[(C2 * 4 + nf) * 32 + l];
                    mma16(P[0][nf], (const uint32_t*)&aa[cur][0], bq.x, bq.y);
                    mma16(P[0][nf], (const uint32_t*)&aa[cur][1], bq.z, bq.w);
                    mma16(P[1][nf], (const uint32_t*)&aa[cur][2], bq.x, bq.y);
                    mma16(P[1][nf], (const uint32_t*)&aa[cur][3], bq.z, bq.w);
                }
            }
            #undef LDA0

            // exchange partner's row-block partial
            #pragma unroll
            for (int nf = 0; nf < 4; ++nf)
                xch[(w * 4 + nf) * 32 + l] = make_float4(P[1 - kh][nf][0], P[1 - kh][nf][1],
                                                          P[1 - kh][nf][2], P[1 - kh][nf][3]);
            // ring back-pressure: h0[e & 7] overwrite needs L1 past e-7 (warp 0 polls)
            if (w == 0 && e >= 8) warp_poll8(g_sub1, 64u * (unsigned)(e - 7));
            __syncthreads();

            float D[4][4];
            #pragma unroll
            for (int nf = 0; nf < 4; ++nf) {
                float4 q = xch[((w ^ 4) * 4 + nf) * 32 + l];
                float b0 = bsm[nf * 8 + 2 * tq];
                float b1 = bsm[nf * 8 + 2 * tq + 1];
                D[nf][0] = P[kh][nf][0] + q.x + b0;
                D[nf][1] = P[kh][nf][1] + q.y + b1;
                D[nf][2] = P[kh][nf][2] + q.z + b0;
                D[nf][3] = P[kh][nf][3] + q.w + b1;
            }
            epi4(D, cst, (char*)g_h0f[e & 7], cta * 8, fin, l);
            group_barrier8(g_sub0, cta, 64u * (unsigned)(e + 1));
        }
    } else {
        // ================= layer 1 group (trails L0) =================
        for (int e = 1; e <= TLEN; ++e) {
            const uint4* Ab;
            int C2base;
            if (kh == 1) {                       // own h1 half — no external wait
                Ab = (e >= 2) ? g_h1f[e & 1] : g_zf;
                C2base = 16;
            } else {                             // h0 half — whole-warp 8-line poll
                warp_poll8(g_sub0, 64u * (unsigned)e);
                Ab = g_h0f[(e - 1) & 7];
                C2base = 0;
            }

            float P[2][4][4];
            #pragma unroll
            for (int m = 0; m < 2; ++m)
                #pragma unroll
                for (int nf = 0; nf < 4; ++nf)
                    #pragma unroll
                    for (int q = 0; q < 4; ++q) P[m][nf][q] = 0.0f;

            uint4 aa[2][4];
            aa[0][0] = __ldcg(&Ab[FIDX(mfA, 0, l)]);
            aa[0][1] = __ldcg(&Ab[FIDX(mfA, 1, l)]);
            aa[0][2] = __ldcg(&Ab[FIDX(mfB, 0, l)]);
            aa[0][3] = __ldcg(&Ab[FIDX(mfB, 1, l)]);
            #pragma unroll
            for (int i = 0; i < 16; ++i) {
                const int cur = i & 1, nxt = cur ^ 1;
                if (i < 15) {
                    const int C = 2 * (i + 1);
                    aa[nxt][0] = __ldcg(&Ab[FIDX(mfA, C,     l)]);
                    aa[nxt][1] = __ldcg(&Ab[FIDX(mfA, C + 1, l)]);
                    aa[nxt][2] = __ldcg(&Ab[FIDX(mfB, C,     l)]);
                    aa[nxt][3] = __ldcg(&Ab[FIDX(mfB, C + 1, l)]);
                }
                const int C2 = C2base + i;
                #pragma unroll
                for (int nf = 0; nf < 4; ++nf) {
                    uint4 bq = Wf[(C2 * 4 + nf) * 32 + l];
                    mma16(P[0][nf], (const uint32_t*)&aa[cur][0], bq.x, bq.y);
                    mma16(P[0][nf], (const uint32_t*)&aa[cur][1], bq.z, bq.w);
                    mma16(P[1][nf], (const uint32_t*)&aa[cur][2], bq.x, bq.y);
                    mma16(P[1][nf], (const uint32_t*)&aa[cur][3], bq.z, bq.w);
                }
            }

            #pragma unroll
            for (int nf = 0; nf < 4; ++nf)
                xch[(w * 4 + nf) * 32 + l] = make_float4(P[1 - kh][nf][0], P[1 - kh][nf][1],
                                                          P[1 - kh][nf][2], P[1 - kh][nf][3]);
            __syncthreads();

            float D[4][4];
            #pragma unroll
            for (int nf = 0; nf < 4; ++nf) {
                float4 q = xch[((w ^ 4) * 4 + nf) * 32 + l];
                float b0 = bsm[nf * 8 + 2 * tq];
                float b1 = bsm[nf * 8 + 2 * tq + 1];
                D[nf][0] = P[kh][nf][0] + q.x + b0;
                D[nf][1] = P[kh][nf][1] + q.y + b1;
                D[nf][2] = P[kh][nf][2] + q.z + b0;
                D[nf][3] = P[kh][nf][3] + q.w + b1;
            }
            epi4(D, cst, (char*)g_h1f[(e - 1) & 1], lc * 8, fin, l);
            group_barrier8(g_sub1, lc, 64u * (unsigned)e);
        }
    }

    // ---------------- FC head on CTA 0 ----------------
    if (cta == 0) {
        if (tid < 32) warp_poll8(g_sub1, 64u * (unsigned)TLEN);
        __syncthreads();
        float* sw = (float*)smc;                     // reuse weight region
        for (int i = tid; i < HD * 32; i += NTHR) {
            int u = i >> 5, j = i & 31;
            sw[i] = fc1w[(size_t)j * HD + u];
        }
        __syncthreads();
        if (tid < BSZ) {
            const uint4* hb = g_h1f[(TLEN - 1) & 1];
            float s[32];
            #pragma unroll
            for (int j = 0; j < 32; ++j) s[j] = 0.0f;
            for (int u = 0; u < HD; ++u) {
                uint4 q = __ldcg(&hb[FIDX(tid >> 4, u >> 4, (tid & 7) * 4 + ((u & 7) >> 1))]);
                uint32_t rg = ((const uint32_t*)&q)[((tid >> 3) & 1) + 2 * ((u >> 3) & 1)];
                float v = __bfloat162float(((const __nv_bfloat16*)&rg)[u & 1]);
                const float4* ww = (const float4*)(sw + u * 32);
                #pragma unroll
                for (int j4 = 0; j4 < 8; ++j4) {
                    float4 wv = ww[j4];
                    s[4 * j4 + 0] += v * wv.x;
                    s[4 * j4 + 1] += v * wv.y;
                    s[4 * j4 + 2] += v * wv.z;
                    s[4 * j4 + 3] += v * wv.w;
                }
            }
            float y = fc2b[0];
            #pragma unroll
            for (int j = 0; j < 32; ++j) y += fc2w[j] * (s[j] + fc1b[j]);
            out[tid] = y;
        }
        __syncthreads();
    }

    // ---------------- finalize: reset counters for graph replay ----------------
    __syncthreads();
    __threadfence();
    if (tid == 0) {
        if (atomicAdd(&g_finp[0], 1u) == NALL - 1) {
            #pragma unroll
            for (int s = 0; s < 8; ++s) { g_sub0[s * 64] = 0; g_sub1[s * 64] = 0; }
            __threadfence();
            atomicExch(&g_finp[0], 0u);
        }
    }
}

// =====================================================================
extern "C" void kernel_launch(void* const* d_in, const int* in_sizes, int n_in,
                              void* d_out, int out_size)
{
    (void)in_sizes; (void)n_in; (void)out_size;
    const float* x    = (const float*)d_in[0];
    const float* Wih0 = (const float*)d_in[1];
    const float* Whh0 = (const float*)d_in[2];
    const float* bih0 = (const float*)d_in[3];
    const float* bhh0 = (const float*)d_in[4];
    const float* Wih1 = (const float*)d_in[5];
    const float* Whh1 = (const float*)d_in[6];
    const float* bih1 = (const float*)d_in[7];
    const float* bhh1 = (const float*)d_in[8];
    const float* fc1w = (const float*)d_in[9];
    const float* fc1b = (const float*)d_in[10];
    const float* fc2w = (const float*)d_in[11];
    const float* fc2b = (const float*)d_in[12];
    float* out = (float*)d_out;

    cudaFuncSetAttribute(rec, cudaFuncAttributeMaxDynamicSharedMemorySize, SMEM_REC);

    xprep<<<TLEN, 256>>>(x);
    rec<<<NALL, NTHR, SMEM_REC>>>(Wih0, Whh0, bih0, bhh0, Wih1, Whh1, bih1, bhh1,
                                  fc1w, fc1b, fc2w, fc2b, out);
}